// round 7
// baseline (speedup 1.0000x reference)
#include <cuda_runtime.h>
#include <cstdint>
#include <math.h>

// NetSimile on 8 block-diagonal graphs of 512 nodes, dense A[4096,4096] in {0,1}.
// Bitset adjacency; neighbor-list (sparse) feature pass; warp-level stats.

#define NN 4096
#define GG 8
#define MM 512
#define WW 16   // 512 bits = 16 u32 words per row
#define LMAX 96 // ego1 list capacity (deg+1; max deg ~35 whp)

__device__ __align__(256) uint32_t g_bits[NN][WW]; // adjacency bitsets (no self bit)
__device__ int   g_deg[NN];
__device__ float g_feat[7][NN];   // slot 3 unused (f3 computed inside k_stats)

// ---------------------------------------------------------------------------
// K1: build per-row bitsets of the diagonal block + degree. One warp per row.
// ---------------------------------------------------------------------------
__global__ void k_bits(const float* __restrict__ A) {
    int warp = (blockIdx.x * blockDim.x + threadIdx.x) >> 5;
    int lane = threadIdx.x & 31;
    if (warp >= NN) return;
    int g = warp / MM;
    const float* row = A + (size_t)warp * NN + (size_t)g * MM;
    uint32_t myword = 0;
    int deg = 0;
#pragma unroll
    for (int w = 0; w < WW; w++) {
        float v = row[w * 32 + lane];
        unsigned m = __ballot_sync(0xffffffffu, v != 0.0f);
        deg += __popc(m);
        if (lane == w) myword = m;
    }
    if (lane < WW) g_bits[warp][lane] = myword;
    if (lane == 0) g_deg[warp] = deg;
}

// ---------------------------------------------------------------------------
// K2: per-node features f0,f1,f2,f4,f5,f6 via neighbor lists.
// One warp per node, 8 warps/block. For node n with ego1 list L (|L|=deg+1):
//   f4_raw   = sum_{v in L} popc(m1 & adj(v))
//   m2       = m1 | OR_{v in L} adj(v)      (v in 2 hops <=> in some nbr's row)
//   sumdeg2  = sum over set bits of m2 of deg;  cnt2 = popc(m2)
// Rows read directly from L2 (g_bits); only deg staged in smem.
// ---------------------------------------------------------------------------
__global__ void __launch_bounds__(256) k_feat() {
    __shared__ int sdeg[MM];
    __shared__ uint16_t slist[8][LMAX];
    int tid = threadIdx.x;
    int wid = tid >> 5, lane = tid & 31;
    int n = blockIdx.x * 8 + wid;
    int g = n >> 9, base = g << 9, r = n - base;

    for (int i = tid; i < MM; i += 256) sdeg[i] = g_deg[base + i];
    __syncthreads();

    // m1 row (adj | self bit): lane<16 holds word 'lane', broadcast to all.
    uint32_t w0 = (lane < WW) ? g_bits[n][lane] : 0u;
    if (lane == (r >> 5)) w0 |= 1u << (r & 31);
    uint32_t m1w[WW];
#pragma unroll
    for (int w = 0; w < WW; w++) m1w[w] = __shfl_sync(0xffffffffu, w0, w);

    // compact ego1 list: exclusive prefix of per-word popcounts
    int pc = (lane < WW) ? __popc(w0) : 0;
    int off = pc;
#pragma unroll
    for (int o = 1; o < 32; o <<= 1) {
        int v = __shfl_up_sync(0xffffffffu, off, o);
        if (lane >= o) off += v;
    }
    int total = __shfl_sync(0xffffffffu, off, 31);   // = deg + 1
    if (total > LMAX) total = LMAX;                  // safety clamp
    off -= pc;
    uint32_t wrem = w0;
    while (wrem) {
        int b = __ffs(wrem) - 1;
        wrem &= wrem - 1;
        if (off < LMAX) slist[wid][off] = (uint16_t)(lane * 32 + b);
        off++;
    }
    __syncwarp();

    int f4 = 0, sumdegn = 0;
    uint32_t or16[WW];
#pragma unroll
    for (int w = 0; w < WW; w++) or16[w] = 0u;

    for (int i = lane; i < total; i += 32) {
        int v = slist[wid][i];
        const uint4* rp = (const uint4*)(g_bits[base + v]);
        uint4 q0 = rp[0], q1 = rp[1], q2 = rp[2], q3 = rp[3];
        uint32_t aw[WW] = {q0.x, q0.y, q0.z, q0.w, q1.x, q1.y, q1.z, q1.w,
                           q2.x, q2.y, q2.z, q2.w, q3.x, q3.y, q3.z, q3.w};
        int p = 0;
#pragma unroll
        for (int w = 0; w < WW; w++) {
            p += __popc(m1w[w] & aw[w]);
            or16[w] |= aw[w];
        }
        f4 += p;
        if (v != r) sumdegn += sdeg[v];
    }
    f4      = __reduce_add_sync(0xffffffffu, f4);
    sumdegn = __reduce_add_sync(0xffffffffu, sumdegn);

    // m2 word 'lane' into lane<16
    uint32_t myw = 0;
#pragma unroll
    for (int w = 0; w < WW; w++) {
        uint32_t t = __reduce_or_sync(0xffffffffu, or16[w]);
        if (lane == w) myw = t | m1w[w];
    }
    int cnt2 = __reduce_add_sync(0xffffffffu, __popc(myw));
    int sumdeg2 = 0;
    uint32_t wr = myw;
    while (wr) {
        int b = __ffs(wr) - 1;
        wr &= wr - 1;
        sumdeg2 += sdeg[lane * 32 + b];
    }
    sumdeg2 = __reduce_add_sync(0xffffffffu, sumdeg2);

    if (lane == 0) {
        float deg = (float)sdeg[r];
        g_feat[0][n] = deg;
        g_feat[1][n] = (deg > 1.f) ? 2.0f * ((float)f4 - deg) / (deg * (deg - 1.0f)) : 0.f;
        g_feat[2][n] = (deg > 0.f) ? (float)sumdegn / deg : 0.f;
        g_feat[4][n] = 0.5f * (float)f4;
        g_feat[5][n] = (float)sumdeg2 - 2.0f * (float)f4;
        g_feat[6][n] = (float)cnt2 - deg - 1.0f;
    }
}

// ---------------------------------------------------------------------------
// K3: per (graph, feature) stats. ONE WARP per (g,f): 56 blocks x 32 threads.
// 16 values per lane in registers. No block barriers, no atomics.
// f==3 warp first computes f3 (neighbor-mean of f1) directly into registers.
// Median: 32-pass binary radix select over register keys (REDUX per pass).
// Moments: fp64 register accumulation + shuffle tree.
// ---------------------------------------------------------------------------
__global__ void __launch_bounds__(32) k_stats(float* __restrict__ out) {
    __shared__ float sf1[MM];
    int id = blockIdx.x;          // 0..55
    int g = id / 7, f = id % 7;
    int lane = threadIdx.x;
    int base = g * MM;

    float xi[16];
    if (f == 3) {
        for (int i = lane; i < MM; i += 32) sf1[i] = g_feat[1][base + i];
        __syncwarp();
#pragma unroll
        for (int j = 0; j < 16; j++) {
            int nd = base + lane + 32 * j;
            const uint4* rp = (const uint4*)(g_bits[nd]);
            uint4 q0 = rp[0], q1 = rp[1], q2 = rp[2], q3 = rp[3];
            uint32_t aw[WW] = {q0.x, q0.y, q0.z, q0.w, q1.x, q1.y, q1.z, q1.w,
                               q2.x, q2.y, q2.z, q2.w, q3.x, q3.y, q3.z, q3.w};
            float s = 0.f;
            int dg = 0;
#pragma unroll
            for (int w = 0; w < WW; w++) {
                uint32_t word = aw[w];
                dg += __popc(word);
                while (word) {
                    int b = __ffs(word) - 1;
                    word &= word - 1;
                    s += sf1[w * 32 + b];
                }
            }
            xi[j] = (dg > 0) ? s / (float)dg : 0.f;
        }
    } else {
#pragma unroll
        for (int j = 0; j < 16; j++) xi[j] = g_feat[f][base + lane + 32 * j];
    }

    // ---- mean (fp64) ------------------------------------------------------
    double sm = 0.0;
#pragma unroll
    for (int j = 0; j < 16; j++) sm += (double)xi[j];
#pragma unroll
    for (int o = 16; o; o >>= 1) sm += __shfl_xor_sync(0xffffffffu, sm, o);
    double meand = sm * (1.0 / (double)MM);
    float mean = (float)meand;

    // ---- median: binary radix select on order-preserving keys -------------
    uint32_t keys[16];
#pragma unroll
    for (int j = 0; j < 16; j++) {
        uint32_t b = __float_as_uint(xi[j]);
        keys[j] = (b & 0x80000000u) ? ~b : (b ^ 0x80000000u);
    }
    uint32_t candm = 0xFFFFu;
    int k = (MM - 1) / 2;   // 255
    uint32_t kv = 0;
    for (int bit = 31; bit >= 0; --bit) {
        int c0 = 0;
#pragma unroll
        for (int j = 0; j < 16; j++)
            c0 += (int)((candm >> j) & (~(keys[j] >> bit)) & 1u);
        c0 = __reduce_add_sync(0xffffffffu, c0);
        uint32_t chosen = (k < c0) ? 0u : 1u;
        if (chosen) k -= c0;
        kv |= chosen << bit;
#pragma unroll
        for (int j = 0; j < 16; j++)
            if (((keys[j] >> bit) & 1u) != chosen) candm &= ~(1u << j);
    }
    uint32_t mb = (kv & 0x80000000u) ? (kv ^ 0x80000000u) : ~kv;
    float medv = __uint_as_float(mb);

    // ---- central moments 2,3,4 (fp32 centered, fp64 accumulation) ---------
    double s2 = 0.0, s3 = 0.0, s4 = 0.0;
#pragma unroll
    for (int j = 0; j < 16; j++) {
        double c = (double)(xi[j] - mean);
        double p = c * c;
        s2 += p; s3 += p * c; s4 += p * p;
    }
#pragma unroll
    for (int o = 16; o; o >>= 1) {
        s2 += __shfl_xor_sync(0xffffffffu, s2, o);
        s3 += __shfl_xor_sync(0xffffffffu, s3, o);
        s4 += __shfl_xor_sync(0xffffffffu, s4, o);
    }

    if (lane == 0) {
        float m2 = (float)(s2 * (1.0 / (double)MM));
        float m3 = (float)(s3 * (1.0 / (double)MM));
        float m4 = (float)(s4 * (1.0 / (double)MM));
        float eps = 1e-4f;
        float sq = sqrtf(m2);
        out[g * 35 + 0  + f] = (float)meand;
        out[g * 35 + 7  + f] = medv;
        out[g * 35 + 14 + f] = sq;
        out[g * 35 + 21 + f] = m3 / fmaxf(m2 * sq, eps);
        out[g * 35 + 28 + f] = m4 / fmaxf(m2 * m2, eps);
    }
}

extern "C" void kernel_launch(void* const* d_in, const int* in_sizes, int n_in,
                              void* d_out, int out_size) {
    const float* A = (const float*)d_in[0];
    float* out = (float*)d_out;

    k_bits<<<NN / 8, 256>>>(A);      // 4096 warps: bitsets + degree
    k_feat<<<NN / 8, 256>>>();       // warp per node, neighbor-list pass
    k_stats<<<GG * 7, 32>>>(out);    // warp per (graph, feature); fused f3
}

// round 8
// speedup vs baseline: 2.2913x; 2.2913x over previous
#include <cuda_runtime.h>
#include <cstdint>
#include <math.h>

// NetSimile on 8 block-diagonal graphs of 512 nodes, dense A[4096,4096] in {0,1}.
// R5 base (dense-smem k_feat + k_f3) with warp-per-(g,f) k_stats.

#define NN 4096
#define GG 8
#define MM 512
#define WW 16   // 512 bits = 16 u32 words per row

__device__ uint32_t g_bits[NN][WW];   // adjacency bitsets (no self bit; diag of A is 0)
__device__ int      g_deg[NN];
__device__ float    g_feat[7][NN];

// ---------------------------------------------------------------------------
// K1: build per-row bitsets of the diagonal block + degree. One warp per row.
// ---------------------------------------------------------------------------
__global__ void k_bits(const float* __restrict__ A) {
    int warp = (blockIdx.x * blockDim.x + threadIdx.x) >> 5;
    int lane = threadIdx.x & 31;
    if (warp >= NN) return;
    int g = warp / MM;
    const float* row = A + (size_t)warp * NN + (size_t)g * MM;
    uint32_t myword = 0;
    int deg = 0;
#pragma unroll
    for (int w = 0; w < WW; w++) {
        float v = row[w * 32 + lane];
        unsigned m = __ballot_sync(0xffffffffu, v != 0.0f);
        deg += __popc(m);
        if (lane == w) myword = m;
    }
    if (lane < WW) g_bits[warp][lane] = myword;
    if (lane == 0) g_deg[warp] = deg;
}

// ---------------------------------------------------------------------------
// K2: per-node features f0,f1,f2,f4,f5,f6. One warp per node, 8 warps/block,
// block's graph bitsets staged in shared (padded to 17 words -> conflict-free).
// (R5 version — measured fast.)
// ---------------------------------------------------------------------------
__global__ void k_feat() {
    __shared__ uint32_t sbits[MM][WW + 1];
    __shared__ int sdeg[MM];
    int tid = threadIdx.x;
    int node0 = blockIdx.x * 8;          // 8 nodes per block, all in same graph
    int g = node0 / MM;
    int base = g * MM;

    for (int idx = tid; idx < MM * WW; idx += 256) {
        int v = idx >> 4, w = idx & 15;
        sbits[v][w] = g_bits[base + v][w];
    }
    for (int idx = tid; idx < MM; idx += 256) sdeg[idx] = g_deg[base + idx];
    __syncthreads();

    int warpId = tid >> 5, lane = tid & 31;
    int n = node0 + warpId;
    int r = n - base;

    uint32_t m1[WW];
#pragma unroll
    for (int w = 0; w < WW; w++) m1[w] = sbits[r][w];
    m1[r >> 5] |= 1u << (r & 31);        // M1 = A | I (self bit)

    int f4 = 0, sumdeg2 = 0, cnt2 = 0, sumdegn = 0;
    for (int v = lane; v < MM; v += 32) {
        int b = 0;
#pragma unroll
        for (int w = 0; w < WW; w++) b += __popc(m1[w] & sbits[v][w]);
        bool m1b = (m1[v >> 5] >> (v & 31)) & 1u;
        bool m2b = m1b || (b > 0);       // M2 = M1 | (B > 0)
        if (m1b) f4 += b;                // (B * M1) row sum
        if (m2b) { cnt2++; sumdeg2 += sdeg[v]; }
        if (m1b && v != r) sumdegn += sdeg[v];   // neighbors only (A bit)
    }
    f4      = __reduce_add_sync(0xffffffffu, f4);
    sumdeg2 = __reduce_add_sync(0xffffffffu, sumdeg2);
    cnt2    = __reduce_add_sync(0xffffffffu, cnt2);
    sumdegn = __reduce_add_sync(0xffffffffu, sumdegn);

    if (lane == 0) {
        float deg = (float)sdeg[r];
        float f0 = deg;
        float f2 = (deg > 0.f) ? (float)sumdegn / deg : 0.f;
        float f1 = (deg > 1.f) ? 2.0f * ((float)f4 - deg) / (deg * (deg - 1.0f)) : 0.f;
        float f4o = 0.5f * (float)f4;
        float f5 = (float)sumdeg2 - 2.0f * (float)f4;
        float f6 = (float)cnt2 - deg - 1.0f;
        g_feat[0][n] = f0;
        g_feat[1][n] = f1;
        g_feat[2][n] = f2;
        g_feat[4][n] = f4o;
        g_feat[5][n] = f5;
        g_feat[6][n] = f6;
    }
}

// ---------------------------------------------------------------------------
// K3: f3 = scatter_mean of neighbor f1. One warp per node; word k is a
// broadcast load, bit 'lane' selects neighbor (k*32+lane). (R5 version.)
// ---------------------------------------------------------------------------
__global__ void k_f3() {
    int warp = (blockIdx.x * blockDim.x + threadIdx.x) >> 5;
    int lane = threadIdx.x & 31;
    if (warp >= NN) return;
    int g = warp / MM;
    int base = g * MM;
    float s = 0.f;
#pragma unroll
    for (int k = 0; k < WW; k++) {
        uint32_t w = g_bits[warp][k];
        if ((w >> lane) & 1u) s += g_feat[1][base + k * 32 + lane];
    }
#pragma unroll
    for (int o = 16; o; o >>= 1) s += __shfl_xor_sync(0xffffffffu, s, o);
    if (lane == 0) {
        float deg = (float)g_deg[warp];
        g_feat[3][warp] = (deg > 0.f) ? s / deg : 0.f;
    }
}

// ---------------------------------------------------------------------------
// K4: per (graph, feature) stats. ONE WARP per (g,f): 56 blocks x 32 threads.
// 16 values per lane in registers. No block barriers, no smem atomics.
// Median: 32-pass binary radix select over register keys (one REDUX per bit).
// Moments: fp64 register accumulation + shuffle tree; fp32 epilogue.
// ---------------------------------------------------------------------------
__global__ void __launch_bounds__(32) k_stats(float* __restrict__ out) {
    int id = blockIdx.x;          // 0..55
    int g = id / 7, f = id % 7;
    int lane = threadIdx.x;
    int base = g * MM;

    float xi[16];
#pragma unroll
    for (int j = 0; j < 16; j++) xi[j] = g_feat[f][base + lane + 32 * j];

    // ---- mean (fp64) ------------------------------------------------------
    double sm = 0.0;
#pragma unroll
    for (int j = 0; j < 16; j++) sm += (double)xi[j];
#pragma unroll
    for (int o = 16; o; o >>= 1) sm += __shfl_xor_sync(0xffffffffu, sm, o);
    double meand = sm * (1.0 / (double)MM);
    float mean = (float)meand;

    // ---- median: binary radix select on order-preserving keys -------------
    uint32_t keys[16];
#pragma unroll
    for (int j = 0; j < 16; j++) {
        uint32_t b = __float_as_uint(xi[j]);
        keys[j] = (b & 0x80000000u) ? ~b : (b ^ 0x80000000u);
    }
    uint32_t candm = 0xFFFFu;
    int k = (MM - 1) / 2;   // 255: lower middle = stable rank 255
    uint32_t kv = 0;
    for (int bit = 31; bit >= 0; --bit) {
        int c0 = 0;
#pragma unroll
        for (int j = 0; j < 16; j++)
            c0 += (int)((candm >> j) & (~(keys[j] >> bit)) & 1u);
        c0 = __reduce_add_sync(0xffffffffu, c0);
        uint32_t chosen = (k < c0) ? 0u : 1u;
        if (chosen) k -= c0;
        kv |= chosen << bit;
#pragma unroll
        for (int j = 0; j < 16; j++)
            if (((keys[j] >> bit) & 1u) != chosen) candm &= ~(1u << j);
    }
    uint32_t mb = (kv & 0x80000000u) ? (kv ^ 0x80000000u) : ~kv;
    float medv = __uint_as_float(mb);

    // ---- central moments 2,3,4 (fp32 centered, fp64 accumulation) ---------
    double s2 = 0.0, s3 = 0.0, s4 = 0.0;
#pragma unroll
    for (int j = 0; j < 16; j++) {
        double c = (double)(xi[j] - mean);
        double p = c * c;
        s2 += p; s3 += p * c; s4 += p * p;
    }
#pragma unroll
    for (int o = 16; o; o >>= 1) {
        s2 += __shfl_xor_sync(0xffffffffu, s2, o);
        s3 += __shfl_xor_sync(0xffffffffu, s3, o);
        s4 += __shfl_xor_sync(0xffffffffu, s4, o);
    }

    if (lane == 0) {
        float m2 = (float)(s2 * (1.0 / (double)MM));
        float m3 = (float)(s3 * (1.0 / (double)MM));
        float m4 = (float)(s4 * (1.0 / (double)MM));
        float eps = 1e-4f;
        float sq = sqrtf(m2);
        out[g * 35 + 0  + f] = (float)meand;
        out[g * 35 + 7  + f] = medv;
        out[g * 35 + 14 + f] = sq;
        out[g * 35 + 21 + f] = m3 / fmaxf(m2 * sq, eps);
        out[g * 35 + 28 + f] = m4 / fmaxf(m2 * m2, eps);
    }
}

extern "C" void kernel_launch(void* const* d_in, const int* in_sizes, int n_in,
                              void* d_out, int out_size) {
    const float* A = (const float*)d_in[0];
    float* out = (float*)d_out;

    k_bits<<<NN / 8, 256>>>(A);      // bitsets + degree
    k_feat<<<NN / 8, 256>>>();       // dense-smem per-node features (R5)
    k_f3<<<NN / 8, 256>>>();         // neighbor-mean of f1 (R5)
    k_stats<<<GG * 7, 32>>>(out);    // warp per (graph, feature)
}

// round 9
// speedup vs baseline: 2.4168x; 1.0548x over previous
#include <cuda_runtime.h>
#include <cstdint>
#include <math.h>

// NetSimile on 8 block-diagonal graphs of 512 nodes, dense A[4096,4096] in {0,1}.
// Bitset adjacency; dense-smem feature pass (R5); warp-level 2-bit-radix stats.

#define NN 4096
#define GG 8
#define MM 512
#define WW 16   // 512 bits = 16 u32 words per row

__device__ uint32_t g_bits[NN][WW];   // adjacency bitsets (no self bit; diag of A is 0)
__device__ int      g_deg[NN];
__device__ float    g_feat[7][NN];

// ---------------------------------------------------------------------------
// K1: build per-row bitsets + degree. One warp per row.
// All 16 LDGs issued before any ballot (MLP=16, no load->ballot serial chain).
// ---------------------------------------------------------------------------
__global__ void k_bits(const float* __restrict__ A) {
    int warp = (blockIdx.x * blockDim.x + threadIdx.x) >> 5;
    int lane = threadIdx.x & 31;
    if (warp >= NN) return;
    int g = warp / MM;
    const float* row = A + (size_t)warp * NN + (size_t)g * MM;

    float v[WW];
#pragma unroll
    for (int w = 0; w < WW; w++) v[w] = row[w * 32 + lane];

    uint32_t myword = 0;
    int deg = 0;
#pragma unroll
    for (int w = 0; w < WW; w++) {
        unsigned m = __ballot_sync(0xffffffffu, v[w] != 0.0f);
        deg += __popc(m);
        if (lane == w) myword = m;
    }
    if (lane < WW) g_bits[warp][lane] = myword;
    if (lane == 0) g_deg[warp] = deg;
}

// ---------------------------------------------------------------------------
// K2: per-node features f0,f1,f2,f4,f5,f6. One warp per node, 8 warps/block,
// block's graph bitsets staged in shared (padded to 17 words -> conflict-free).
// ---------------------------------------------------------------------------
__global__ void k_feat() {
    __shared__ uint32_t sbits[MM][WW + 1];
    __shared__ int sdeg[MM];
    int tid = threadIdx.x;
    int node0 = blockIdx.x * 8;          // 8 nodes per block, all in same graph
    int g = node0 / MM;
    int base = g * MM;

    for (int idx = tid; idx < MM * WW; idx += 256) {
        int v = idx >> 4, w = idx & 15;
        sbits[v][w] = g_bits[base + v][w];
    }
    for (int idx = tid; idx < MM; idx += 256) sdeg[idx] = g_deg[base + idx];
    __syncthreads();

    int warpId = tid >> 5, lane = tid & 31;
    int n = node0 + warpId;
    int r = n - base;

    uint32_t m1[WW];
#pragma unroll
    for (int w = 0; w < WW; w++) m1[w] = sbits[r][w];
    m1[r >> 5] |= 1u << (r & 31);        // M1 = A | I (self bit)

    int f4 = 0, sumdeg2 = 0, cnt2 = 0, sumdegn = 0;
    for (int v = lane; v < MM; v += 32) {
        int b = 0;
#pragma unroll
        for (int w = 0; w < WW; w++) b += __popc(m1[w] & sbits[v][w]);
        bool m1b = (m1[v >> 5] >> (v & 31)) & 1u;
        bool m2b = m1b || (b > 0);       // M2 = M1 | (B > 0)
        if (m1b) f4 += b;                // (B * M1) row sum
        if (m2b) { cnt2++; sumdeg2 += sdeg[v]; }
        if (m1b && v != r) sumdegn += sdeg[v];   // neighbors only (A bit)
    }
    f4      = __reduce_add_sync(0xffffffffu, f4);
    sumdeg2 = __reduce_add_sync(0xffffffffu, sumdeg2);
    cnt2    = __reduce_add_sync(0xffffffffu, cnt2);
    sumdegn = __reduce_add_sync(0xffffffffu, sumdegn);

    if (lane == 0) {
        float deg = (float)sdeg[r];
        g_feat[0][n] = deg;
        g_feat[1][n] = (deg > 1.f) ? 2.0f * ((float)f4 - deg) / (deg * (deg - 1.0f)) : 0.f;
        g_feat[2][n] = (deg > 0.f) ? (float)sumdegn / deg : 0.f;
        g_feat[4][n] = 0.5f * (float)f4;
        g_feat[5][n] = (float)sumdeg2 - 2.0f * (float)f4;
        g_feat[6][n] = (float)cnt2 - deg - 1.0f;
    }
}

// ---------------------------------------------------------------------------
// K3: f3 = scatter_mean of neighbor f1. One warp per node.
// ---------------------------------------------------------------------------
__global__ void k_f3() {
    int warp = (blockIdx.x * blockDim.x + threadIdx.x) >> 5;
    int lane = threadIdx.x & 31;
    if (warp >= NN) return;
    int g = warp / MM;
    int base = g * MM;
    float s = 0.f;
#pragma unroll
    for (int k = 0; k < WW; k++) {
        uint32_t w = g_bits[warp][k];
        if ((w >> lane) & 1u) s += g_feat[1][base + k * 32 + lane];
    }
#pragma unroll
    for (int o = 16; o; o >>= 1) s += __shfl_xor_sync(0xffffffffu, s, o);
    if (lane == 0) {
        float deg = (float)g_deg[warp];
        g_feat[3][warp] = (deg > 0.f) ? s / deg : 0.f;
    }
}

// ---------------------------------------------------------------------------
// K4: per (graph, feature) stats. ONE WARP per (g,f), 16 values per lane.
// Median: 2-bit radix select over register keys, with candidate min==max
// REDUX early exit (collapses in ~4-6 passes for unique values AND tie
// classes). Moments: fp64 register accumulation + shuffle tree.
// ---------------------------------------------------------------------------
__global__ void __launch_bounds__(32) k_stats(float* __restrict__ out) {
    int id = blockIdx.x;          // 0..55
    int g = id / 7, f = id % 7;
    int lane = threadIdx.x;
    int base = g * MM;
    const unsigned FULL = 0xffffffffu;

    float xi[16];
#pragma unroll
    for (int j = 0; j < 16; j++) xi[j] = g_feat[f][base + lane + 32 * j];

    // ---- mean (fp64) ------------------------------------------------------
    double sm = 0.0;
#pragma unroll
    for (int j = 0; j < 16; j++) sm += (double)xi[j];
#pragma unroll
    for (int o = 16; o; o >>= 1) sm += __shfl_xor_sync(FULL, sm, o);
    double meand = sm * (1.0 / (double)MM);
    float mean = (float)meand;

    // ---- median: 2-bit radix select with min/max early exit ---------------
    uint32_t keys[16];
#pragma unroll
    for (int j = 0; j < 16; j++) {
        uint32_t b = __float_as_uint(xi[j]);
        keys[j] = (b & 0x80000000u) ? ~b : (b ^ 0x80000000u);
    }
    uint32_t candm = 0xFFFFu;
    int k = (MM - 1) / 2;   // 255: value at sorted index 255
    uint32_t kv = 0;

    for (int bit = 30; bit >= 0; bit -= 2) {
        uint32_t mn = 0xFFFFFFFFu, mx = 0u, cnt = 0, bb = 0;
#pragma unroll
        for (int j = 0; j < 16; j++) {
            uint32_t kj = keys[j];
            uint32_t b = (kj >> bit) & 3u;
            bb |= b << (2 * j);
            if ((candm >> j) & 1u) {
                mn = min(mn, kj);
                mx = max(mx, kj);
                cnt += (b < 3u) ? (1u << (10 * b)) : 0u;  // c0|c1<<10|c2<<20
            }
        }
        mn = __reduce_min_sync(FULL, mn);
        mx = __reduce_max_sync(FULL, mx);
        if (mn == mx) { kv = mn; break; }   // all candidates share one value
        cnt = __reduce_add_sync(FULL, cnt);
        int c0 = cnt & 1023, c1 = (cnt >> 10) & 1023, c2 = (cnt >> 20) & 1023;
        uint32_t chosen;
        if (k < c0)                 { chosen = 0u; }
        else if (k < c0 + c1)       { chosen = 1u; k -= c0; }
        else if (k < c0 + c1 + c2)  { chosen = 2u; k -= c0 + c1; }
        else                        { chosen = 3u; k -= c0 + c1 + c2; }
        kv |= chosen << bit;
#pragma unroll
        for (int j = 0; j < 16; j++)
            if (((bb >> (2 * j)) & 3u) != chosen) candm &= ~(1u << j);
    }
    uint32_t mb = (kv & 0x80000000u) ? (kv ^ 0x80000000u) : ~kv;
    float medv = __uint_as_float(mb);

    // ---- central moments 2,3,4 (fp32 centered, fp64 accumulation) ---------
    double s2 = 0.0, s3 = 0.0, s4 = 0.0;
#pragma unroll
    for (int j = 0; j < 16; j++) {
        double c = (double)(xi[j] - mean);
        double p = c * c;
        s2 += p; s3 += p * c; s4 += p * p;
    }
#pragma unroll
    for (int o = 16; o; o >>= 1) {
        s2 += __shfl_xor_sync(FULL, s2, o);
        s3 += __shfl_xor_sync(FULL, s3, o);
        s4 += __shfl_xor_sync(FULL, s4, o);
    }

    if (lane == 0) {
        float m2 = (float)(s2 * (1.0 / (double)MM));
        float m3 = (float)(s3 * (1.0 / (double)MM));
        float m4 = (float)(s4 * (1.0 / (double)MM));
        float eps = 1e-4f;
        float sq = sqrtf(m2);
        out[g * 35 + 0  + f] = (float)meand;
        out[g * 35 + 7  + f] = medv;
        out[g * 35 + 14 + f] = sq;
        out[g * 35 + 21 + f] = m3 / fmaxf(m2 * sq, eps);
        out[g * 35 + 28 + f] = m4 / fmaxf(m2 * m2, eps);
    }
}

extern "C" void kernel_launch(void* const* d_in, const int* in_sizes, int n_in,
                              void* d_out, int out_size) {
    const float* A = (const float*)d_in[0];
    float* out = (float*)d_out;

    k_bits<<<NN / 8, 256>>>(A);      // bitsets + degree (MLP-16 loads)
    k_feat<<<NN / 8, 256>>>();       // dense-smem per-node features
    k_f3<<<NN / 8, 256>>>();         // neighbor-mean of f1
    k_stats<<<GG * 7, 32>>>(out);    // warp per (graph, feature)
}

// round 10
// speedup vs baseline: 2.8135x; 1.1641x over previous
#include <cuda_runtime.h>
#include <cstdint>
#include <math.h>

// NetSimile on 8 block-diagonal graphs of 512 nodes, dense A[4096,4096] in {0,1}.
// Bitset adjacency; dense-smem feature pass; warp-level all-fp32 stats.

#define NN 4096
#define GG 8
#define MM 512
#define WW 16   // 512 bits = 16 u32 words per row

__device__ uint32_t g_bits[NN][WW];   // adjacency bitsets (no self bit; diag of A is 0)
__device__ int      g_deg[NN];
__device__ float    g_feat[7][NN];

// ---------------------------------------------------------------------------
// K1: build per-row bitsets + degree. One warp per row, MLP-16 loads.
// ---------------------------------------------------------------------------
__global__ void k_bits(const float* __restrict__ A) {
    int warp = (blockIdx.x * blockDim.x + threadIdx.x) >> 5;
    int lane = threadIdx.x & 31;
    if (warp >= NN) return;
    int g = warp / MM;
    const float* row = A + (size_t)warp * NN + (size_t)g * MM;

    float v[WW];
#pragma unroll
    for (int w = 0; w < WW; w++) v[w] = row[w * 32 + lane];

    uint32_t myword = 0;
    int deg = 0;
#pragma unroll
    for (int w = 0; w < WW; w++) {
        unsigned m = __ballot_sync(0xffffffffu, v[w] != 0.0f);
        deg += __popc(m);
        if (lane == w) myword = m;
    }
    if (lane < WW) g_bits[warp][lane] = myword;
    if (lane == 0) g_deg[warp] = deg;
}

// ---------------------------------------------------------------------------
// K2: per-node features f0,f1,f2,f4,f5,f6. One warp per node, 8 warps/block,
// block's graph bitsets staged in shared (padded to 17 words -> conflict-free).
// ---------------------------------------------------------------------------
__global__ void k_feat() {
    __shared__ uint32_t sbits[MM][WW + 1];
    __shared__ int sdeg[MM];
    int tid = threadIdx.x;
    int node0 = blockIdx.x * 8;          // 8 nodes per block, all in same graph
    int g = node0 / MM;
    int base = g * MM;

    for (int idx = tid; idx < MM * WW; idx += 256) {
        int v = idx >> 4, w = idx & 15;
        sbits[v][w] = g_bits[base + v][w];
    }
    for (int idx = tid; idx < MM; idx += 256) sdeg[idx] = g_deg[base + idx];
    __syncthreads();

    int warpId = tid >> 5, lane = tid & 31;
    int n = node0 + warpId;
    int r = n - base;

    uint32_t m1[WW];
#pragma unroll
    for (int w = 0; w < WW; w++) m1[w] = sbits[r][w];
    m1[r >> 5] |= 1u << (r & 31);        // M1 = A | I (self bit)

    int f4 = 0, sumdeg2 = 0, cnt2 = 0, sumdegn = 0;
    for (int v = lane; v < MM; v += 32) {
        int b = 0;
#pragma unroll
        for (int w = 0; w < WW; w++) b += __popc(m1[w] & sbits[v][w]);
        bool m1b = (m1[v >> 5] >> (v & 31)) & 1u;
        bool m2b = m1b || (b > 0);       // M2 = M1 | (B > 0)
        if (m1b) f4 += b;                // (B * M1) row sum
        if (m2b) { cnt2++; sumdeg2 += sdeg[v]; }
        if (m1b && v != r) sumdegn += sdeg[v];   // neighbors only (A bit)
    }
    f4      = __reduce_add_sync(0xffffffffu, f4);
    sumdeg2 = __reduce_add_sync(0xffffffffu, sumdeg2);
    cnt2    = __reduce_add_sync(0xffffffffu, cnt2);
    sumdegn = __reduce_add_sync(0xffffffffu, sumdegn);

    if (lane == 0) {
        float deg = (float)sdeg[r];
        g_feat[0][n] = deg;
        g_feat[1][n] = (deg > 1.f) ? 2.0f * ((float)f4 - deg) / (deg * (deg - 1.0f)) : 0.f;
        g_feat[2][n] = (deg > 0.f) ? (float)sumdegn / deg : 0.f;
        g_feat[4][n] = 0.5f * (float)f4;
        g_feat[5][n] = (float)sumdeg2 - 2.0f * (float)f4;
        g_feat[6][n] = (float)cnt2 - deg - 1.0f;
    }
}

// ---------------------------------------------------------------------------
// K3: f3 = scatter_mean of neighbor f1. One warp per node.
// ---------------------------------------------------------------------------
__global__ void k_f3() {
    int warp = (blockIdx.x * blockDim.x + threadIdx.x) >> 5;
    int lane = threadIdx.x & 31;
    if (warp >= NN) return;
    int g = warp / MM;
    int base = g * MM;
    float s = 0.f;
#pragma unroll
    for (int k = 0; k < WW; k++) {
        uint32_t w = g_bits[warp][k];
        if ((w >> lane) & 1u) s += g_feat[1][base + k * 32 + lane];
    }
#pragma unroll
    for (int o = 16; o; o >>= 1) s += __shfl_xor_sync(0xffffffffu, s, o);
    if (lane == 0) {
        float deg = (float)g_deg[warp];
        g_feat[3][warp] = (deg > 0.f) ? s / deg : 0.f;
    }
}

// ---------------------------------------------------------------------------
// K4: per (graph, feature) stats. ONE WARP per (g,f), 16 values per lane.
// ALL FP32 (fp64 DADD lat ~47-64 made 16-deep accumulator chains + fp64
// shuffle trees the dominant serial-latency term at occ=1.6%; FADD lat=4).
// Accuracy: per-lane 16-add + 5-level pairwise tree ~1e-6 rel, gate is 1e-3.
// Median: 2-bit radix select over register keys with min/max early exit.
// ---------------------------------------------------------------------------
__global__ void __launch_bounds__(32) k_stats(float* __restrict__ out) {
    int id = blockIdx.x;          // 0..55
    int g = id / 7, f = id % 7;
    int lane = threadIdx.x;
    int base = g * MM;
    const unsigned FULL = 0xffffffffu;

    float xi[16];
#pragma unroll
    for (int j = 0; j < 16; j++) xi[j] = g_feat[f][base + lane + 32 * j];

    // ---- mean (fp32, pairwise per-lane then tree) --------------------------
    float pair8[8];
#pragma unroll
    for (int j = 0; j < 8; j++) pair8[j] = xi[2 * j] + xi[2 * j + 1];
    float q4a = (pair8[0] + pair8[1]) + (pair8[2] + pair8[3]);
    float q4b = (pair8[4] + pair8[5]) + (pair8[6] + pair8[7]);
    float sm = q4a + q4b;
#pragma unroll
    for (int o = 16; o; o >>= 1) sm += __shfl_xor_sync(FULL, sm, o);
    float mean = sm * (1.0f / (float)MM);

    // ---- median: 2-bit radix select with min/max early exit ---------------
    uint32_t keys[16];
#pragma unroll
    for (int j = 0; j < 16; j++) {
        uint32_t b = __float_as_uint(xi[j]);
        keys[j] = (b & 0x80000000u) ? ~b : (b ^ 0x80000000u);
    }
    uint32_t candm = 0xFFFFu;
    int k = (MM - 1) / 2;   // 255: value at sorted index 255
    uint32_t kv = 0;

    for (int bit = 30; bit >= 0; bit -= 2) {
        uint32_t mn = 0xFFFFFFFFu, mx = 0u, cnt = 0, bb = 0;
#pragma unroll
        for (int j = 0; j < 16; j++) {
            uint32_t kj = keys[j];
            uint32_t b = (kj >> bit) & 3u;
            bb |= b << (2 * j);
            if ((candm >> j) & 1u) {
                mn = min(mn, kj);
                mx = max(mx, kj);
                cnt += (b < 3u) ? (1u << (10 * b)) : 0u;  // c0|c1<<10|c2<<20
            }
        }
        mn = __reduce_min_sync(FULL, mn);
        mx = __reduce_max_sync(FULL, mx);
        if (mn == mx) { kv = mn; break; }   // all candidates share one value
        cnt = __reduce_add_sync(FULL, cnt);
        int c0 = cnt & 1023, c1 = (cnt >> 10) & 1023, c2 = (cnt >> 20) & 1023;
        uint32_t chosen;
        if (k < c0)                 { chosen = 0u; }
        else if (k < c0 + c1)       { chosen = 1u; k -= c0; }
        else if (k < c0 + c1 + c2)  { chosen = 2u; k -= c0 + c1; }
        else                        { chosen = 3u; k -= c0 + c1 + c2; }
        kv |= chosen << bit;
#pragma unroll
        for (int j = 0; j < 16; j++)
            if (((bb >> (2 * j)) & 3u) != chosen) candm &= ~(1u << j);
    }
    uint32_t mb = (kv & 0x80000000u) ? (kv ^ 0x80000000u) : ~kv;
    float medv = __uint_as_float(mb);

    // ---- central moments 2,3,4 (fp32, pairwise-ish) ------------------------
    float a2[8], a3[8], a4[8];
#pragma unroll
    for (int j = 0; j < 8; j++) {
        float c0 = xi[2 * j] - mean,  c1 = xi[2 * j + 1] - mean;
        float p0 = c0 * c0,           p1 = c1 * c1;
        a2[j] = p0 + p1;
        a3[j] = fmaf(p0, c0, p1 * c1);
        a4[j] = fmaf(p0, p0, p1 * p1);
    }
    float s2 = ((a2[0]+a2[1])+(a2[2]+a2[3])) + ((a2[4]+a2[5])+(a2[6]+a2[7]));
    float s3 = ((a3[0]+a3[1])+(a3[2]+a3[3])) + ((a3[4]+a3[5])+(a3[6]+a3[7]));
    float s4 = ((a4[0]+a4[1])+(a4[2]+a4[3])) + ((a4[4]+a4[5])+(a4[6]+a4[7]));
#pragma unroll
    for (int o = 16; o; o >>= 1) {
        s2 += __shfl_xor_sync(FULL, s2, o);
        s3 += __shfl_xor_sync(FULL, s3, o);
        s4 += __shfl_xor_sync(FULL, s4, o);
    }

    if (lane == 0) {
        float m2 = s2 * (1.0f / (float)MM);
        float m3 = s3 * (1.0f / (float)MM);
        float m4 = s4 * (1.0f / (float)MM);
        float eps = 1e-4f;
        float sq = sqrtf(m2);
        out[g * 35 + 0  + f] = mean;
        out[g * 35 + 7  + f] = medv;
        out[g * 35 + 14 + f] = sq;
        out[g * 35 + 21 + f] = m3 / fmaxf(m2 * sq, eps);
        out[g * 35 + 28 + f] = m4 / fmaxf(m2 * m2, eps);
    }
}

extern "C" void kernel_launch(void* const* d_in, const int* in_sizes, int n_in,
                              void* d_out, int out_size) {
    const float* A = (const float*)d_in[0];
    float* out = (float*)d_out;

    k_bits<<<NN / 8, 256>>>(A);      // bitsets + degree (MLP-16 loads)
    k_feat<<<NN / 8, 256>>>();       // dense-smem per-node features
    k_f3<<<NN / 8, 256>>>();         // neighbor-mean of f1
    k_stats<<<GG * 7, 32>>>(out);    // warp per (graph, feature), all-fp32
}